// round 15
// baseline (speedup 1.0000x reference)
#include <cuda_runtime.h>
#include <cstdint>

// HashGrid encode: 16 levels, F=2, T=2^19, base_res=16, per_level_scale=2.0,
// smoothstep, 2D. Levels 0..5 dense, 6..15 hashed.
//
// v15 = v14 (78.3us: fused 8-level halves, block 128, long-work-first) with
// a UNIFORM BRANCH-FREE load path replacing the per-level even/odd divergent
// branch (which cost BSSY/BSYNC serialization every level and fenced ptxas's
// cross-level load batching):
//   every entry lives in quad[idx>>1]; the row's second corner shares that
//   quad iff (i10>>1)==(i00>>1) (true for even-x; handles dense wrap too).
//   -> 2 unconditional LDG.128 + 2 predicated LDG.128 + hi/lo SELs per level.
// Same wavefront count, zero divergence, unified dense/hashed load code.

#define NLEVELS 16
#define LOG2_T 19
#define TSIZE (1u << LOG2_T)
#define PRIME1 2654435761u

template <int L_BEGIN>
__device__ __forceinline__ void half_body(
    int i, int lane, float x0, float x1,
    const float2* __restrict__ table,
    float* __restrict__ out, int n)
{
    float acc[16];

#pragma unroll
    for (int k = 0; k < 8; ++k) {
        const int l = L_BEGIN + k;
        const unsigned res = 16u << l;                 // power of two
        const float scale = (float)(res - 1u);

        float p0 = x0 * scale + 0.5f;
        float p1 = x1 * scale + 0.5f;
        float fl0 = floorf(p0);
        float fl1 = floorf(p1);
        float fr0 = p0 - fl0;
        float fr1 = p1 - fl1;
        unsigned g0 = (unsigned)(int)fl0;
        unsigned g1 = (unsigned)(int)fl1;

        // smoothstep weights
        float w0 = fr0 * fr0 * (3.0f - 2.0f * fr0);
        float w1 = fr1 * fr1 * (3.0f - 2.0f * fr1);

        unsigned i00, i10, i01, i11;
        if (l <= 5) {
            const unsigned mask = (res * res) - 1u;
            unsigned b0 = g0 + g1 * res;
            unsigned b1 = b0 + res;
            i00 = b0 & mask;        i10 = (b0 + 1u) & mask;
            i01 = b1 & mask;        i11 = (b1 + 1u) & mask;
        } else {
            const unsigned hmask = TSIZE - 1u;
            unsigned hy0 = g1 * PRIME1;
            unsigned hy1 = hy0 + PRIME1;
            i00 = (g0 ^ hy0) & hmask;        i10 = ((g0 + 1u) ^ hy0) & hmask;
            i01 = (g0 ^ hy1) & hmask;        i11 = ((g0 + 1u) ^ hy1) & hmask;
        }

        // ---- uniform branch-free gather: entry idx lives in quad[idx>>1] ----
        const float4* tq = reinterpret_cast<const float4*>(table + (size_t)l * TSIZE);
        const unsigned q00 = i00 >> 1, q10 = i10 >> 1;
        const unsigned q01 = i01 >> 1, q11 = i11 >> 1;

        float4 v00 = __ldg(tq + q00);
        float4 v01 = __ldg(tq + q01);
        float4 v10 = v00;
        if (q10 != q00) v10 = __ldg(tq + q10);   // predicated LDG, no branch
        float4 v11 = v01;
        if (q11 != q01) v11 = __ldg(tq + q11);

        float2 f00 = (i00 & 1u) ? make_float2(v00.z, v00.w) : make_float2(v00.x, v00.y);
        float2 f10 = (i10 & 1u) ? make_float2(v10.z, v10.w) : make_float2(v10.x, v10.y);
        float2 f01 = (i01 & 1u) ? make_float2(v01.z, v01.w) : make_float2(v01.x, v01.y);
        float2 f11 = (i11 & 1u) ? make_float2(v11.z, v11.w) : make_float2(v11.x, v11.y);

        float c00 = (1.0f - w0) * (1.0f - w1);
        float c10 = w0 * (1.0f - w1);
        float c01 = (1.0f - w0) * w1;
        float c11 = w0 * w1;

        acc[2 * k]     = c00 * f00.x + c10 * f10.x + c01 * f01.x + c11 * f11.x;
        acc[2 * k + 1] = c00 * f00.y + c10 * f10.y + c01 * f01.y + c11 * f11.y;
    }

    const int wbase = i & ~31;   // first point of this warp
    if (wbase + 32 <= n) {
        // 16x16 butterfly transpose within each half-warp.
#pragma unroll
        for (int step = 1; step < 16; step <<= 1) {
            const bool up = (lane & step) != 0;
#pragma unroll
            for (int t = 0; t < 16; ++t) {
                if ((t & step) == 0) {
                    float lo = acc[t], hi = acc[t + step];
                    float send = up ? lo : hi;
                    float recv = __shfl_xor_sync(0xffffffffu, send, step);
                    if (up) acc[t] = recv; else acc[t + step] = recv;
                }
            }
        }
        // lanes 0..15 -> point (wbase+j) channels [2*L_BEGIN..+16),
        // lanes 16..31 -> point (wbase+16+j). 64B contiguous per half-warp.
        const int c0 = 2 * L_BEGIN;
        float* ob = out + (size_t)(wbase + (lane >> 4) * 16) * 32 + c0 + (lane & 15);
#pragma unroll
        for (int j = 0; j < 16; ++j)
            ob[j * 32] = acc[j];
    } else {
        // tail warp (not hit for N = 524288)
        float* ot = out + (size_t)i * 32 + 2 * L_BEGIN;
#pragma unroll
        for (int c = 0; c < 16; ++c) ot[c] = acc[c];
    }
}

__global__ void hashgrid_fused_kernel(
    const float2* __restrict__ x,          // [N] points in [-1,1]
    const float2* __restrict__ table,      // [16 * T] float2 entries
    float* __restrict__ out,               // [N, 32]
    int n,
    int blocks_per_half)
{
    const int lane = threadIdx.x & 31;
    // Long-work-first: first half of the grid = hashed levels 8..15.
    const bool hashed_half = (blockIdx.x < blocks_per_half);
    const int blk = hashed_half ? blockIdx.x : (blockIdx.x - blocks_per_half);
    const int i = blk * blockDim.x + threadIdx.x;
    if (i >= n) return;

    float2 xi = __ldg(&x[i]);
    float x0 = xi.x * 0.5f + 0.5f;
    float x1 = xi.y * 0.5f + 0.5f;

    if (hashed_half)
        half_body<8>(i, lane, x0, x1, table, out, n);
    else
        half_body<0>(i, lane, x0, x1, table, out, n);
}

extern "C" void kernel_launch(void* const* d_in, const int* in_sizes, int n_in,
                              void* d_out, int out_size)
{
    const float2* x     = (const float2*)d_in[0];   // [N,2] float32
    const float2* table = (const float2*)d_in[1];   // [16, T, 2] float32
    float* out          = (float*)d_out;            // [N, 32] float32

    int n = in_sizes[0] / 2;
    int threads = 128;
    int blocks = (n + threads - 1) / threads;
    hashgrid_fused_kernel<<<2 * blocks, threads>>>(x, table, out, n, blocks);
}

// round 16
// speedup vs baseline: 1.1846x; 1.1846x over previous
#include <cuda_runtime.h>
#include <cstdint>

// HashGrid encode: 16 levels, F=2, T=2^19, base_res=16, per_level_scale=2.0,
// smoothstep, 2D. Levels 0..5 dense, 6..15 hashed.
//
// v16 = v14 (78.3us best: fused 8-level halves, block 128, long-work-first,
// pair-merged gathers with per-level even/odd branch, half-warp transpose
// stores) + STREAMING cache hints:
//   __stcs on all output stores (64MB written once, never re-read) and
//   __ldcs on the x reads. Output lines stop displacing the 64MB of hash
//   tables in the 126MB L2 -> higher gather hit rate -> less latency
//   exposure (the measured ~20% L1-idle).
// v15 lesson: do NOT unify the even/odd load paths (odd lanes' LDG.128
// doubled their sector traffic; the branch was cheap). Body = v14 verbatim.

#define NLEVELS 16
#define LOG2_T 19
#define TSIZE (1u << LOG2_T)
#define PRIME1 2654435761u

template <int L_BEGIN>
__device__ __forceinline__ void half_body(
    int i, int lane, float x0, float x1,
    const float2* __restrict__ table,
    float* __restrict__ out, int n)
{
    float acc[16];

#pragma unroll
    for (int k = 0; k < 8; ++k) {
        const int l = L_BEGIN + k;
        const unsigned res = 16u << l;                 // power of two
        const float scale = (float)(res - 1u);

        float p0 = x0 * scale + 0.5f;
        float p1 = x1 * scale + 0.5f;
        float fl0 = floorf(p0);
        float fl1 = floorf(p1);
        float fr0 = p0 - fl0;
        float fr1 = p1 - fl1;
        unsigned g0 = (unsigned)(int)fl0;
        unsigned g1 = (unsigned)(int)fl1;

        // smoothstep weights
        float w0 = fr0 * fr0 * (3.0f - 2.0f * fr0);
        float w1 = fr1 * fr1 * (3.0f - 2.0f * fr1);

        unsigned i00, i10, i01, i11;
        if (l <= 5) {
            const unsigned mask = (res * res) - 1u;
            unsigned b0 = g0 + g1 * res;
            unsigned b1 = b0 + res;
            i00 = b0 & mask;        i10 = (b0 + 1u) & mask;
            i01 = b1 & mask;        i11 = (b1 + 1u) & mask;
        } else {
            const unsigned hmask = TSIZE - 1u;
            unsigned hy0 = g1 * PRIME1;
            unsigned hy1 = hy0 + PRIME1;
            i00 = (g0 ^ hy0) & hmask;        i10 = ((g0 + 1u) ^ hy0) & hmask;
            i01 = (g0 ^ hy1) & hmask;        i11 = ((g0 + 1u) ^ hy1) & hmask;
        }

        const float2* tl = table + (size_t)l * TSIZE;
        float2 f00, f10, f01, f11;

        if ((g0 & 1u) == 0u) {
            // x even: row corners are adjacent 8B entries -> one aligned float4.
            // Dense levels: i00/i01 provably even. Hashed: may be odd -> swap.
            const float4* tl4 = reinterpret_cast<const float4*>(tl);
            float4 v0 = __ldg(tl4 + (i00 >> 1));
            float4 v1 = __ldg(tl4 + (i01 >> 1));
            if (l <= 5) {
                f00 = make_float2(v0.x, v0.y); f10 = make_float2(v0.z, v0.w);
                f01 = make_float2(v1.x, v1.y); f11 = make_float2(v1.z, v1.w);
            } else {
                if (i00 & 1u) { f00 = make_float2(v0.z, v0.w); f10 = make_float2(v0.x, v0.y); }
                else          { f00 = make_float2(v0.x, v0.y); f10 = make_float2(v0.z, v0.w); }
                if (i01 & 1u) { f01 = make_float2(v1.z, v1.w); f11 = make_float2(v1.x, v1.y); }
                else          { f01 = make_float2(v1.x, v1.y); f11 = make_float2(v1.z, v1.w); }
            }
        } else {
            f00 = __ldg(tl + i00);
            f10 = __ldg(tl + i10);
            f01 = __ldg(tl + i01);
            f11 = __ldg(tl + i11);
        }

        float c00 = (1.0f - w0) * (1.0f - w1);
        float c10 = w0 * (1.0f - w1);
        float c01 = (1.0f - w0) * w1;
        float c11 = w0 * w1;

        acc[2 * k]     = c00 * f00.x + c10 * f10.x + c01 * f01.x + c11 * f11.x;
        acc[2 * k + 1] = c00 * f00.y + c10 * f10.y + c01 * f01.y + c11 * f11.y;
    }

    const int wbase = i & ~31;   // first point of this warp
    if (wbase + 32 <= n) {
        // 16x16 butterfly transpose within each half-warp.
#pragma unroll
        for (int step = 1; step < 16; step <<= 1) {
            const bool up = (lane & step) != 0;
#pragma unroll
            for (int t = 0; t < 16; ++t) {
                if ((t & step) == 0) {
                    float lo = acc[t], hi = acc[t + step];
                    float send = up ? lo : hi;
                    float recv = __shfl_xor_sync(0xffffffffu, send, step);
                    if (up) acc[t] = recv; else acc[t + step] = recv;
                }
            }
        }
        // lanes 0..15 -> point (wbase+j) channels [2*L_BEGIN..+16),
        // lanes 16..31 -> point (wbase+16+j). 64B contiguous per half-warp.
        // Streaming stores: evict-first, don't displace table lines in L2.
        const int c0 = 2 * L_BEGIN;
        float* ob = out + (size_t)(wbase + (lane >> 4) * 16) * 32 + c0 + (lane & 15);
#pragma unroll
        for (int j = 0; j < 16; ++j)
            __stcs(&ob[j * 32], acc[j]);
    } else {
        // tail warp (not hit for N = 524288)
        float* ot = out + (size_t)i * 32 + 2 * L_BEGIN;
#pragma unroll
        for (int c = 0; c < 16; ++c) __stcs(&ot[c], acc[c]);
    }
}

__global__ void hashgrid_fused_kernel(
    const float2* __restrict__ x,          // [N] points in [-1,1]
    const float2* __restrict__ table,      // [16 * T] float2 entries
    float* __restrict__ out,               // [N, 32]
    int n,
    int blocks_per_half)
{
    const int lane = threadIdx.x & 31;
    // Long-work-first: first half of the grid = hashed levels 8..15.
    const bool hashed_half = (blockIdx.x < blocks_per_half);
    const int blk = hashed_half ? blockIdx.x : (blockIdx.x - blocks_per_half);
    const int i = blk * blockDim.x + threadIdx.x;
    if (i >= n) return;

    float2 xi = __ldcs(&x[i]);   // streamed: read once per half, never reused
    float x0 = xi.x * 0.5f + 0.5f;
    float x1 = xi.y * 0.5f + 0.5f;

    if (hashed_half)
        half_body<8>(i, lane, x0, x1, table, out, n);
    else
        half_body<0>(i, lane, x0, x1, table, out, n);
}

extern "C" void kernel_launch(void* const* d_in, const int* in_sizes, int n_in,
                              void* d_out, int out_size)
{
    const float2* x     = (const float2*)d_in[0];   // [N,2] float32
    const float2* table = (const float2*)d_in[1];   // [16, T, 2] float32
    float* out          = (float*)d_out;            // [N, 32] float32

    int n = in_sizes[0] / 2;
    int threads = 128;
    int blocks = (n + threads - 1) / threads;
    hashgrid_fused_kernel<<<2 * blocks, threads>>>(x, table, out, n, blocks);
}